// round 14
// baseline (speedup 1.0000x reference)
#include <cuda_runtime.h>

// crossMSEloss: B=4, S=256, P=64, D=63
// out[b,s] = sum_p conf[p] * min_q ||pred_p - tgt_q||
//          + sum_q min_p ( ||pred_p - tgt_q|| / conf[p] )
//
// GEMM-form (norm trick), dot matrix on tensor cores via split-tf32
// mma.sync.m16n8k8, 3 products (hihi+hilo+lohi, err ~2^-22).
// R14: BOTH operands pre-split once (preds in registers at the front end)
// into packed uint2{tf32_hi, tf32_lo} smem planes -> mainloop has zero
// ALU split work: 4 LDS.64(A) + 8 LDS.64(B) + 12 MMA per k-step.

#define ST 68   // uint2 row stride for both planes

// dynamic smem layout (bytes)
#define OFF_TA    0          // uint2 [64][68] preds   = 34816
#define OFF_TQ    34816      // uint2 [64][68] targets = 34816
#define OFF_PN    69632      // float[64]
#define OFF_QN    69888      // float[64]
#define OFF_CONF  70144      // float[64]
#define OFF_CI2   70400      // float[64]
#define OFF_RM2   70656      // float[128]
#define OFF_CM2   71168      // float[256]
#define OFF_RED   72192      // float[128]
#define SMEM_BYTES 72704

__device__ __forceinline__ unsigned tf32_of(float x) {
    unsigned r; asm("cvt.rna.tf32.f32 %0, %1;" : "=r"(r) : "f"(x)); return r;
}
__device__ __forceinline__ uint2 split_tf32(float x) {
    uint2 v;
    v.x = tf32_of(x);
    v.y = tf32_of(x - __uint_as_float(v.x));
    return v;
}
__device__ __forceinline__ void mma_tf32(float c[4], const unsigned a[4],
                                         unsigned b0, unsigned b1) {
    asm("mma.sync.aligned.m16n8k8.row.col.f32.tf32.tf32.f32 "
        "{%0,%1,%2,%3}, {%4,%5,%6,%7}, {%8,%9}, {%0,%1,%2,%3};"
        : "+f"(c[0]), "+f"(c[1]), "+f"(c[2]), "+f"(c[3])
        : "r"(a[0]), "r"(a[1]), "r"(a[2]), "r"(a[3]), "r"(b0), "r"(b1));
}

__global__ __launch_bounds__(256)
void cross_mse_loss_kernel(const float* __restrict__ inp,
                           const float* __restrict__ tgt,
                           float* __restrict__ out)
{
    extern __shared__ __align__(16) char smraw[];
    uint2* ta   = (uint2*)(smraw + OFF_TA);     // preds   [p][d] {hi,lo}
    uint2* tq   = (uint2*)(smraw + OFF_TQ);     // targets [q][d] {hi,lo}
    float* pn   = (float*)(smraw + OFF_PN);
    float* qn   = (float*)(smraw + OFF_QN);
    float* conf = (float*)(smraw + OFF_CONF);
    float* ci2s = (float*)(smraw + OFF_CI2);
    float* rm2  = (float*)(smraw + OFF_RM2);
    float* cm2  = (float*)(smraw + OFF_CM2);
    float* red  = (float*)(smraw + OFF_RED);

    const int bs   = blockIdx.x;
    const int tid  = threadIdx.x;
    const int lane = tid & 31;
    const int w    = tid >> 5;
    const int g    = lane >> 2;
    const int i4   = lane & 3;
    const int mi   = w & 3;       // m-stripe: rows 16*mi..+15
    const int ch   = w >> 2;      // col half: cols 32*ch..+31
    const int l15  = tid & 15;

    const float* ip = inp + (size_t)bs * 4096;
    const float* tp = tgt + (size_t)bs * 4032;

    // ================= Front end: batched gmem loads =================
    const float4* ip4 = (const float4*)ip;
    const float4* tp4 = (const float4*)tp;

    float4 pv[4];
    #pragma unroll
    for (int r = 0; r < 4; r++) pv[r] = ip4[tid + r * 256];
    float4 tv[4];
    #pragma unroll
    for (int r = 0; r < 4; r++) {
        int idx = tid + r * 256;
        tv[r] = (idx < 1008) ? tp4[idx] : make_float4(0.f, 0.f, 0.f, 0.f);
    }

    if (tid < 64) tq[tid * ST + 63] = make_uint2(0u, 0u);   // d=63 pad (targets)

    // ---- Preds: split in registers, store uint2 plane; pn via 16-lane shfl ----
    #pragma unroll
    for (int r = 0; r < 4; r++) {
        int idx = tid + r * 256;
        int p   = idx >> 4;
        int d4  = l15 << 2;
        float4 v = pv[r];
        float s;
        if (d4 == 60) {
            conf[p] = v.w;
            float ci = 1.0f / v.w;
            ci2s[p] = ci * ci;
            v.w = 0.0f;
            s = fmaf(v.x, v.x, fmaf(v.y, v.y, v.z * v.z));
        } else {
            s = fmaf(v.x, v.x, fmaf(v.y, v.y, fmaf(v.z, v.z, v.w * v.w)));
        }
        uint2 s0 = split_tf32(v.x), s1 = split_tf32(v.y);
        uint2 s2 = split_tf32(v.z), s3 = split_tf32(v.w);
        uint2* dst = ta + p * ST + d4;
        *(uint4*)(dst)     = make_uint4(s0.x, s0.y, s1.x, s1.y);
        *(uint4*)(dst + 2) = make_uint4(s2.x, s2.y, s3.x, s3.y);
        #pragma unroll
        for (int m = 1; m < 16; m <<= 1)
            s += __shfl_xor_sync(0xFFFFFFFFu, s, m);
        if (l15 == 0) pn[p] = s;
    }

    // ---- Targets: split once, scatter uint2 plane ----
    #pragma unroll
    for (int r = 0; r < 4; r++) {
        int idx = tid + r * 256;
        if (idx < 1008) {
            int e0 = idx << 2;
            float vv[4] = {tv[r].x, tv[r].y, tv[r].z, tv[r].w};
            #pragma unroll
            for (int c = 0; c < 4; c++) {
                int e = e0 + c;
                int q = e / 63;
                int d = e - q * 63;
                tq[q * ST + d] = split_tf32(vv[c]);
            }
        }
    }
    __syncthreads();

    // ---- qn: 4 threads per q (quarters of d), combine via 2 shuffles ----
    {
        const int q  = tid >> 2;          // lane>>2 pattern: 8 q per warp
        const int qt = tid & 3;           // d-quarter
        const uint2* bp = tq + q * ST + qt * 16;
        float s = 0.0f;
        #pragma unroll
        for (int dd = 0; dd < 16; dd++) {
            uint2 v = bp[dd];
            float b = __uint_as_float(v.x) + __uint_as_float(v.y);
            s = fmaf(b, b, s);
        }
        s += __shfl_xor_sync(0xFFFFFFFFu, s, 1);
        s += __shfl_xor_sync(0xFFFFFFFFu, s, 2);
        if (qt == 0) qn[q] = s;
    }
    __syncthreads();

    // ============ Tensor-core mainloop: split-tf32, 3 products ============
    float c[4][4];
    #pragma unroll
    for (int j = 0; j < 4; j++)
        #pragma unroll
        for (int e = 0; e < 4; e++) c[j][e] = 0.0f;

    const uint2* arow = ta + (mi * 16 + g) * ST;
    const uint2* brow = tq + (ch * 32 + g) * ST;

    #pragma unroll
    for (int ks = 0; ks < 8; ks++) {
        const int k0 = ks * 8;
        uint2 a0 = arow[k0 + i4];
        uint2 a1 = arow[8 * ST + k0 + i4];
        uint2 a2 = arow[k0 + i4 + 4];
        uint2 a3 = arow[8 * ST + k0 + i4 + 4];
        unsigned ahi[4] = {a0.x, a1.x, a2.x, a3.x};
        unsigned alo[4] = {a0.y, a1.y, a2.y, a3.y};
        #pragma unroll
        for (int j = 0; j < 4; j++) {
            uint2 b0 = brow[j * 8 * ST + k0 + i4];
            uint2 b1 = brow[j * 8 * ST + k0 + i4 + 4];
            mma_tf32(c[j], ahi, b0.x, b1.x);   // hi*hi
            mma_tf32(c[j], ahi, b0.y, b1.y);   // hi*lo
            mma_tf32(c[j], alo, b0.x, b1.x);   // lo*hi
        }
    }

    // ================= Epilogue: d^2 + mins =================
    const int r1 = mi * 16 + g;
    const int r2 = r1 + 8;
    const float pn1 = pn[r1], pn2 = pn[r2];
    const float ci1 = ci2s[r1], ci2v = ci2s[r2];

    float rmin1 = 1e30f, rmin2 = 1e30f;
    float cmin[8];
    #pragma unroll
    for (int j = 0; j < 4; j++) {
        const int cb = ch * 32 + j * 8 + 2 * i4;
        const float qn0 = qn[cb], qn1 = qn[cb + 1];
        float d11 = fmaxf(fmaf(-2.0f, c[j][0], pn1 + qn0), 0.0f);
        float d12 = fmaxf(fmaf(-2.0f, c[j][1], pn1 + qn1), 0.0f);
        float d21 = fmaxf(fmaf(-2.0f, c[j][2], pn2 + qn0), 0.0f);
        float d22 = fmaxf(fmaf(-2.0f, c[j][3], pn2 + qn1), 0.0f);
        rmin1 = fminf(rmin1, fminf(d11, d12));
        rmin2 = fminf(rmin2, fminf(d21, d22));
        cmin[2 * j]     = fminf(d11 * ci1, d21 * ci2v);
        cmin[2 * j + 1] = fminf(d12 * ci1, d22 * ci2v);
    }

    rmin1 = fminf(rmin1, __shfl_xor_sync(0xFFFFFFFFu, rmin1, 1));
    rmin1 = fminf(rmin1, __shfl_xor_sync(0xFFFFFFFFu, rmin1, 2));
    rmin2 = fminf(rmin2, __shfl_xor_sync(0xFFFFFFFFu, rmin2, 1));
    rmin2 = fminf(rmin2, __shfl_xor_sync(0xFFFFFFFFu, rmin2, 2));
    if (i4 == 0) {
        rm2[ch * 64 + r1] = rmin1;
        rm2[ch * 64 + r2] = rmin2;
    }
    #pragma unroll
    for (int u = 0; u < 8; u++) {
        cmin[u] = fminf(cmin[u], __shfl_xor_sync(0xFFFFFFFFu, cmin[u], 4));
        cmin[u] = fminf(cmin[u], __shfl_xor_sync(0xFFFFFFFFu, cmin[u], 8));
        cmin[u] = fminf(cmin[u], __shfl_xor_sync(0xFFFFFFFFu, cmin[u], 16));
    }
    if (g == 0) {
        #pragma unroll
        for (int j = 0; j < 4; j++) {
            cm2[mi * 64 + ch * 32 + j * 8 + 2 * i4]     = cmin[2 * j];
            cm2[mi * 64 + ch * 32 + j * 8 + 2 * i4 + 1] = cmin[2 * j + 1];
        }
    }
    __syncthreads();

    // ================= Final: 128 sqrts + block sum =================
    float val = 0.0f;
    if (tid < 64) {
        val = conf[tid] * sqrtf(fminf(rm2[tid], rm2[64 + tid]));
    } else if (tid < 128) {
        int q = tid - 64;
        float m = fminf(fminf(cm2[q], cm2[64 + q]),
                        fminf(cm2[128 + q], cm2[192 + q]));
        val = sqrtf(m);
    }

    if (tid < 128) red[tid] = val;
    __syncthreads();
    if (tid < 64) red[tid] += red[tid + 64];
    __syncthreads();
    if (tid < 32) {
        float s = red[tid] + red[tid + 32];
        #pragma unroll
        for (int off = 16; off > 0; off >>= 1)
            s += __shfl_down_sync(0xFFFFFFFFu, s, off);
        if (tid == 0) out[bs] = s;
    }
}

extern "C" void kernel_launch(void* const* d_in, const int* in_sizes, int n_in,
                              void* d_out, int out_size)
{
    const float* inp = (const float*)d_in[0];
    const float* tgt = (const float*)d_in[1];
    float* out = (float*)d_out;

    cudaFuncSetAttribute(cross_mse_loss_kernel,
                         cudaFuncAttributeMaxDynamicSharedMemorySize,
                         SMEM_BYTES);
    cross_mse_loss_kernel<<<1024, 256, SMEM_BYTES>>>(inp, tgt, out);
}

// round 15
// speedup vs baseline: 1.6000x; 1.6000x over previous
#include <cuda_runtime.h>

// crossMSEloss: B=4, S=256, P=64, D=63
// out[b,s] = sum_p conf[p] * min_q ||pred_p - tgt_q||
//          + sum_q min_p ( ||pred_p - tgt_q|| / conf[p] )
//
// GEMM-form (norm trick), dot matrix on tensor cores via split-tf32
// mma.sync.m16n8k8, 3 products (hihi + hilo + lohi).
// R15 = R12 structure with a cheap truncation split: hi = x & 0xFFFFE000
// (LOP3; exact tf32, low bits zero), lo = x - hi (FADD; HW truncates its
// low mantissa bits on read). 2 ops/element instead of 3, split across
// alu+fma pipes -- attacks R12's ALU-pipe binder (41%) directly.

#define SP_S 68

__device__ __forceinline__ void split_tf32(float x, unsigned& hi, unsigned& lo) {
    unsigned xb = __float_as_uint(x);
    hi = xb & 0xFFFFE000u;                       // LOP3: tf32 by truncation
    lo = __float_as_uint(x - __uint_as_float(hi));  // FADD: exact residual
}
__device__ __forceinline__ void mma_tf32(float c[4], const unsigned a[4],
                                         unsigned b0, unsigned b1) {
    asm("mma.sync.aligned.m16n8k8.row.col.f32.tf32.tf32.f32 "
        "{%0,%1,%2,%3}, {%4,%5,%6,%7}, {%8,%9}, {%0,%1,%2,%3};"
        : "+f"(c[0]), "+f"(c[1]), "+f"(c[2]), "+f"(c[3])
        : "r"(a[0]), "r"(a[1]), "r"(a[2]), "r"(a[3]), "r"(b0), "r"(b1));
}

__global__ __launch_bounds__(256, 4)
void cross_mse_loss_kernel(const float* __restrict__ inp,
                           const float* __restrict__ tgt,
                           float* __restrict__ out)
{
    __shared__ __align__(16) float sp[64 * SP_S];   // preds [p][d], d63 -> 0
    __shared__ __align__(16) float tq[64 * SP_S];   // targets [q][d], d63 -> 0
    __shared__ float pn[64], qn[64], conf[64], ci2s[64];
    __shared__ float rm2[2 * 64];    // per-col-half row mins (d^2)
    __shared__ float cm2[4 * 64];    // per-m-stripe col mins (d^2 * ci2)
    __shared__ float red[128];

    const int bs   = blockIdx.x;
    const int tid  = threadIdx.x;
    const int lane = tid & 31;
    const int w    = tid >> 5;
    const int g    = lane >> 2;      // fragment group
    const int i4   = lane & 3;       // thread-in-group
    const int mi   = w & 3;          // m-stripe: rows 16*mi..+15
    const int ch   = w >> 2;         // col half: cols 32*ch..+31

    const float* ip = inp + (size_t)bs * 4096;
    const float* tp = tgt + (size_t)bs * 4032;

    // ================= Front end: batched gmem loads =================
    const float4* ip4 = (const float4*)ip;
    const float4* tp4 = (const float4*)tp;

    float4 pv[4];
    #pragma unroll
    for (int r = 0; r < 4; r++) pv[r] = ip4[tid + r * 256];
    float4 tv[4];
    #pragma unroll
    for (int r = 0; r < 4; r++) {
        int idx = tid + r * 256;
        tv[r] = (idx < 1008) ? tp4[idx] : make_float4(0.f, 0.f, 0.f, 0.f);
    }

    if (tid < 64) tq[tid * SP_S + 63] = 0.0f;   // d=63 pad

    // preds -> sp (STS.128); conf on d4==60 lane
    #pragma unroll
    for (int r = 0; r < 4; r++) {
        int idx = tid + r * 256;
        int p   = idx >> 4;
        int d4  = (idx & 15) << 2;
        float4 v = pv[r];
        if (d4 == 60) {
            conf[p] = v.w;
            float ci = 1.0f / v.w;
            ci2s[p] = ci * ci;
            v.w = 0.0f;
        }
        *(float4*)(sp + p * SP_S + d4) = v;
    }
    // targets -> tq[q][d]
    #pragma unroll
    for (int r = 0; r < 4; r++) {
        int idx = tid + r * 256;
        if (idx < 1008) {
            int e0 = idx << 2;
            float vv[4] = {tv[r].x, tv[r].y, tv[r].z, tv[r].w};
            #pragma unroll
            for (int c = 0; c < 4; c++) {
                int e = e0 + c;
                int q = e / 63;
                int d = e - q * 63;
                tq[q * SP_S + d] = vv[c];
            }
        }
    }
    __syncthreads();

    // ================= Norms =================
    if (tid < 64) {
        const float4* ap = (const float4*)(sp + tid * SP_S);
        float s = 0.0f;
        #pragma unroll
        for (int k = 0; k < 16; k++) {
            float4 a = ap[k];
            s = fmaf(a.x, a.x, fmaf(a.y, a.y, fmaf(a.z, a.z, fmaf(a.w, a.w, s))));
        }
        pn[tid] = s;
    } else if (tid < 128) {
        const float4* bp = (const float4*)(tq + (tid - 64) * SP_S);
        float s = 0.0f;
        #pragma unroll
        for (int k = 0; k < 16; k++) {
            float4 b = bp[k];
            s = fmaf(b.x, b.x, fmaf(b.y, b.y, fmaf(b.z, b.z, fmaf(b.w, b.w, s))));
        }
        qn[tid - 64] = s;
    }
    __syncthreads();

    // ============ Tensor-core mainloop: split-tf32, 3 products ============
    float c[4][4];
    #pragma unroll
    for (int j = 0; j < 4; j++)
        #pragma unroll
        for (int e = 0; e < 4; e++) c[j][e] = 0.0f;

    const float* arow = sp + (mi * 16 + g) * SP_S;
    const float* brow = tq + (ch * 32 + g) * SP_S;

    #pragma unroll
    for (int ks = 0; ks < 8; ks++) {
        const int k0 = ks * 8;
        float af0 = arow[k0 + i4];
        float af1 = arow[8 * SP_S + k0 + i4];
        float af2 = arow[k0 + i4 + 4];
        float af3 = arow[8 * SP_S + k0 + i4 + 4];
        unsigned ahi[4], alo[4];
        split_tf32(af0, ahi[0], alo[0]);
        split_tf32(af1, ahi[1], alo[1]);
        split_tf32(af2, ahi[2], alo[2]);
        split_tf32(af3, ahi[3], alo[3]);
        #pragma unroll
        for (int j = 0; j < 4; j++) {
            float bf0 = brow[j * 8 * SP_S + k0 + i4];
            float bf1 = brow[j * 8 * SP_S + k0 + i4 + 4];
            unsigned bh0, bl0, bh1, bl1;
            split_tf32(bf0, bh0, bl0);
            split_tf32(bf1, bh1, bl1);
            mma_tf32(c[j], ahi, bh0, bh1);   // hi*hi
            mma_tf32(c[j], ahi, bl0, bl1);   // hi*lo
            mma_tf32(c[j], alo, bh0, bh1);   // lo*hi
        }
    }

    // ================= Epilogue: d^2 + mins =================
    const int r1 = mi * 16 + g;
    const int r2 = r1 + 8;
    const float pn1 = pn[r1], pn2 = pn[r2];
    const float ci1 = ci2s[r1], ci2v = ci2s[r2];

    float rmin1 = 1e30f, rmin2 = 1e30f;
    float cmin[8];
    #pragma unroll
    for (int j = 0; j < 4; j++) {
        const int cb = ch * 32 + j * 8 + 2 * i4;
        const float qn0 = qn[cb], qn1 = qn[cb + 1];
        float d11 = fmaxf(fmaf(-2.0f, c[j][0], pn1 + qn0), 0.0f);
        float d12 = fmaxf(fmaf(-2.0f, c[j][1], pn1 + qn1), 0.0f);
        float d21 = fmaxf(fmaf(-2.0f, c[j][2], pn2 + qn0), 0.0f);
        float d22 = fmaxf(fmaf(-2.0f, c[j][3], pn2 + qn1), 0.0f);
        rmin1 = fminf(rmin1, fminf(d11, d12));
        rmin2 = fminf(rmin2, fminf(d21, d22));
        cmin[2 * j]     = fminf(d11 * ci1, d21 * ci2v);
        cmin[2 * j + 1] = fminf(d12 * ci1, d22 * ci2v);
    }

    rmin1 = fminf(rmin1, __shfl_xor_sync(0xFFFFFFFFu, rmin1, 1));
    rmin1 = fminf(rmin1, __shfl_xor_sync(0xFFFFFFFFu, rmin1, 2));
    rmin2 = fminf(rmin2, __shfl_xor_sync(0xFFFFFFFFu, rmin2, 1));
    rmin2 = fminf(rmin2, __shfl_xor_sync(0xFFFFFFFFu, rmin2, 2));
    if (i4 == 0) {
        rm2[ch * 64 + r1] = rmin1;
        rm2[ch * 64 + r2] = rmin2;
    }
    #pragma unroll
    for (int u = 0; u < 8; u++) {
        cmin[u] = fminf(cmin[u], __shfl_xor_sync(0xFFFFFFFFu, cmin[u], 4));
        cmin[u] = fminf(cmin[u], __shfl_xor_sync(0xFFFFFFFFu, cmin[u], 8));
        cmin[u] = fminf(cmin[u], __shfl_xor_sync(0xFFFFFFFFu, cmin[u], 16));
    }
    if (g == 0) {
        #pragma unroll
        for (int j = 0; j < 4; j++) {
            cm2[mi * 64 + ch * 32 + j * 8 + 2 * i4]     = cmin[2 * j];
            cm2[mi * 64 + ch * 32 + j * 8 + 2 * i4 + 1] = cmin[2 * j + 1];
        }
    }
    __syncthreads();

    // ================= Final: 128 sqrts + block sum =================
    float val = 0.0f;
    if (tid < 64) {
        val = conf[tid] * sqrtf(fminf(rm2[tid], rm2[64 + tid]));
    } else if (tid < 128) {
        int q = tid - 64;
        float m = fminf(fminf(cm2[q], cm2[64 + q]),
                        fminf(cm2[128 + q], cm2[192 + q]));
        val = sqrtf(m);
    }

    if (tid < 128) red[tid] = val;
    __syncthreads();
    if (tid < 64) red[tid] += red[tid + 64];
    __syncthreads();
    if (tid < 32) {
        float s = red[tid] + red[tid + 32];
        #pragma unroll
        for (int off = 16; off > 0; off >>= 1)
            s += __shfl_down_sync(0xFFFFFFFFu, s, off);
        if (tid == 0) out[bs] = s;
    }
}

extern "C" void kernel_launch(void* const* d_in, const int* in_sizes, int n_in,
                              void* d_out, int out_size)
{
    const float* inp = (const float*)d_in[0];
    const float* tgt = (const float*)d_in[1];
    float* out = (float*)d_out;
    cross_mse_loss_kernel<<<1024, 256>>>(inp, tgt, out);
}

// round 16
// speedup vs baseline: 1.6151x; 1.0094x over previous
#include <cuda_runtime.h>

// crossMSEloss: B=4, S=256, P=64, D=63
// out[b,s] = sum_p conf[p] * min_q ||pred_p - tgt_q||
//          + sum_q min_p ( ||pred_p - tgt_q|| / conf[p] )
//
// GEMM-form (norm trick), dot matrix on tensor cores via split-tf32
// mma.sync.m16n8k8, 3 products (hihi + hilo + lohi).
// Truncation split: hi = x & 0xFFFFE000 (LOP3), lo = x - hi (FADD) -- 2 ops
// across 2 pipes. R16 = R15 + occupancy 4 -> 5 blocks/SM (regs capped 51;
// smem 38KB x 5 = 190KB fits) to cover LDS->split->MMA latency chains.

#define SP_S 68

__device__ __forceinline__ void split_tf32(float x, unsigned& hi, unsigned& lo) {
    unsigned xb = __float_as_uint(x);
    hi = xb & 0xFFFFE000u;                          // LOP3: tf32 by truncation
    lo = __float_as_uint(x - __uint_as_float(hi));  // FADD: exact residual
}
__device__ __forceinline__ void mma_tf32(float c[4], const unsigned a[4],
                                         unsigned b0, unsigned b1) {
    asm("mma.sync.aligned.m16n8k8.row.col.f32.tf32.tf32.f32 "
        "{%0,%1,%2,%3}, {%4,%5,%6,%7}, {%8,%9}, {%0,%1,%2,%3};"
        : "+f"(c[0]), "+f"(c[1]), "+f"(c[2]), "+f"(c[3])
        : "r"(a[0]), "r"(a[1]), "r"(a[2]), "r"(a[3]), "r"(b0), "r"(b1));
}

__global__ __launch_bounds__(256, 5)
void cross_mse_loss_kernel(const float* __restrict__ inp,
                           const float* __restrict__ tgt,
                           float* __restrict__ out)
{
    __shared__ __align__(16) float sp[64 * SP_S];   // preds [p][d], d63 -> 0
    __shared__ __align__(16) float tq[64 * SP_S];   // targets [q][d], d63 -> 0
    __shared__ float pn[64], qn[64], conf[64], ci2s[64];
    __shared__ float rm2[2 * 64];    // per-col-half row mins (d^2)
    __shared__ float cm2[4 * 64];    // per-m-stripe col mins (d^2 * ci2)
    __shared__ float red[128];

    const int bs   = blockIdx.x;
    const int tid  = threadIdx.x;
    const int lane = tid & 31;
    const int w    = tid >> 5;
    const int g    = lane >> 2;      // fragment group
    const int i4   = lane & 3;       // thread-in-group
    const int mi   = w & 3;          // m-stripe: rows 16*mi..+15
    const int ch   = w >> 2;         // col half: cols 32*ch..+31

    const float* ip = inp + (size_t)bs * 4096;
    const float* tp = tgt + (size_t)bs * 4032;

    // ================= Front end: batched gmem loads =================
    const float4* ip4 = (const float4*)ip;
    const float4* tp4 = (const float4*)tp;

    float4 pv[4];
    #pragma unroll
    for (int r = 0; r < 4; r++) pv[r] = ip4[tid + r * 256];
    float4 tv[4];
    #pragma unroll
    for (int r = 0; r < 4; r++) {
        int idx = tid + r * 256;
        tv[r] = (idx < 1008) ? tp4[idx] : make_float4(0.f, 0.f, 0.f, 0.f);
    }

    if (tid < 64) tq[tid * SP_S + 63] = 0.0f;   // d=63 pad

    // preds -> sp (STS.128); conf on d4==60 lane
    #pragma unroll
    for (int r = 0; r < 4; r++) {
        int idx = tid + r * 256;
        int p   = idx >> 4;
        int d4  = (idx & 15) << 2;
        float4 v = pv[r];
        if (d4 == 60) {
            conf[p] = v.w;
            float ci = 1.0f / v.w;
            ci2s[p] = ci * ci;
            v.w = 0.0f;
        }
        *(float4*)(sp + p * SP_S + d4) = v;
    }
    // targets -> tq[q][d]
    #pragma unroll
    for (int r = 0; r < 4; r++) {
        int idx = tid + r * 256;
        if (idx < 1008) {
            int e0 = idx << 2;
            float vv[4] = {tv[r].x, tv[r].y, tv[r].z, tv[r].w};
            #pragma unroll
            for (int c = 0; c < 4; c++) {
                int e = e0 + c;
                int q = e / 63;
                int d = e - q * 63;
                tq[q * SP_S + d] = vv[c];
            }
        }
    }
    __syncthreads();

    // ================= Norms =================
    if (tid < 64) {
        const float4* ap = (const float4*)(sp + tid * SP_S);
        float s = 0.0f;
        #pragma unroll
        for (int k = 0; k < 16; k++) {
            float4 a = ap[k];
            s = fmaf(a.x, a.x, fmaf(a.y, a.y, fmaf(a.z, a.z, fmaf(a.w, a.w, s))));
        }
        pn[tid] = s;
    } else if (tid < 128) {
        const float4* bp = (const float4*)(tq + (tid - 64) * SP_S);
        float s = 0.0f;
        #pragma unroll
        for (int k = 0; k < 16; k++) {
            float4 b = bp[k];
            s = fmaf(b.x, b.x, fmaf(b.y, b.y, fmaf(b.z, b.z, fmaf(b.w, b.w, s))));
        }
        qn[tid - 64] = s;
    }
    __syncthreads();

    // ============ Tensor-core mainloop: split-tf32, 3 products ============
    float c[4][4];
    #pragma unroll
    for (int j = 0; j < 4; j++)
        #pragma unroll
        for (int e = 0; e < 4; e++) c[j][e] = 0.0f;

    const float* arow = sp + (mi * 16 + g) * SP_S;
    const float* brow = tq + (ch * 32 + g) * SP_S;

    #pragma unroll
    for (int ks = 0; ks < 8; ks++) {
        const int k0 = ks * 8;
        float af0 = arow[k0 + i4];
        float af1 = arow[8 * SP_S + k0 + i4];
        float af2 = arow[k0 + i4 + 4];
        float af3 = arow[8 * SP_S + k0 + i4 + 4];
        unsigned ahi[4], alo[4];
        split_tf32(af0, ahi[0], alo[0]);
        split_tf32(af1, ahi[1], alo[1]);
        split_tf32(af2, ahi[2], alo[2]);
        split_tf32(af3, ahi[3], alo[3]);
        #pragma unroll
        for (int j = 0; j < 4; j++) {
            float bf0 = brow[j * 8 * SP_S + k0 + i4];
            float bf1 = brow[j * 8 * SP_S + k0 + i4 + 4];
            unsigned bh0, bl0, bh1, bl1;
            split_tf32(bf0, bh0, bl0);
            split_tf32(bf1, bh1, bl1);
            mma_tf32(c[j], ahi, bh0, bh1);   // hi*hi
            mma_tf32(c[j], ahi, bl0, bl1);   // hi*lo
            mma_tf32(c[j], alo, bh0, bh1);   // lo*hi
        }
    }

    // ================= Epilogue: d^2 + mins =================
    const int r1 = mi * 16 + g;
    const int r2 = r1 + 8;
    const float pn1 = pn[r1], pn2 = pn[r2];
    const float ci1 = ci2s[r1], ci2v = ci2s[r2];

    float rmin1 = 1e30f, rmin2 = 1e30f;
    float cmin[8];
    #pragma unroll
    for (int j = 0; j < 4; j++) {
        const int cb = ch * 32 + j * 8 + 2 * i4;
        const float qn0 = qn[cb], qn1 = qn[cb + 1];
        float d11 = fmaxf(fmaf(-2.0f, c[j][0], pn1 + qn0), 0.0f);
        float d12 = fmaxf(fmaf(-2.0f, c[j][1], pn1 + qn1), 0.0f);
        float d21 = fmaxf(fmaf(-2.0f, c[j][2], pn2 + qn0), 0.0f);
        float d22 = fmaxf(fmaf(-2.0f, c[j][3], pn2 + qn1), 0.0f);
        rmin1 = fminf(rmin1, fminf(d11, d12));
        rmin2 = fminf(rmin2, fminf(d21, d22));
        cmin[2 * j]     = fminf(d11 * ci1, d21 * ci2v);
        cmin[2 * j + 1] = fminf(d12 * ci1, d22 * ci2v);
    }

    rmin1 = fminf(rmin1, __shfl_xor_sync(0xFFFFFFFFu, rmin1, 1));
    rmin1 = fminf(rmin1, __shfl_xor_sync(0xFFFFFFFFu, rmin1, 2));
    rmin2 = fminf(rmin2, __shfl_xor_sync(0xFFFFFFFFu, rmin2, 1));
    rmin2 = fminf(rmin2, __shfl_xor_sync(0xFFFFFFFFu, rmin2, 2));
    if (i4 == 0) {
        rm2[ch * 64 + r1] = rmin1;
        rm2[ch * 64 + r2] = rmin2;
    }
    #pragma unroll
    for (int u = 0; u < 8; u++) {
        cmin[u] = fminf(cmin[u], __shfl_xor_sync(0xFFFFFFFFu, cmin[u], 4));
        cmin[u] = fminf(cmin[u], __shfl_xor_sync(0xFFFFFFFFu, cmin[u], 8));
        cmin[u] = fminf(cmin[u], __shfl_xor_sync(0xFFFFFFFFu, cmin[u], 16));
    }
    if (g == 0) {
        #pragma unroll
        for (int j = 0; j < 4; j++) {
            cm2[mi * 64 + ch * 32 + j * 8 + 2 * i4]     = cmin[2 * j];
            cm2[mi * 64 + ch * 32 + j * 8 + 2 * i4 + 1] = cmin[2 * j + 1];
        }
    }
    __syncthreads();

    // ================= Final: 128 sqrts + block sum =================
    float val = 0.0f;
    if (tid < 64) {
        val = conf[tid] * sqrtf(fminf(rm2[tid], rm2[64 + tid]));
    } else if (tid < 128) {
        int q = tid - 64;
        float m = fminf(fminf(cm2[q], cm2[64 + q]),
                        fminf(cm2[128 + q], cm2[192 + q]));
        val = sqrtf(m);
    }

    if (tid < 128) red[tid] = val;
    __syncthreads();
    if (tid < 64) red[tid] += red[tid + 64];
    __syncthreads();
    if (tid < 32) {
        float s = red[tid] + red[tid + 32];
        #pragma unroll
        for (int off = 16; off > 0; off >>= 1)
            s += __shfl_down_sync(0xFFFFFFFFu, s, off);
        if (tid == 0) out[bs] = s;
    }
}

extern "C" void kernel_launch(void* const* d_in, const int* in_sizes, int n_in,
                              void* d_out, int out_size)
{
    const float* inp = (const float*)d_in[0];
    const float* tgt = (const float*)d_in[1];
    float* out = (float*)d_out;
    cross_mse_loss_kernel<<<1024, 256>>>(inp, tgt, out);
}